// round 14
// baseline (speedup 1.0000x reference)
#include <cuda_runtime.h>
#include <cuda_fp16.h>
#include <math.h>
#include <math_constants.h>
#include <stdint.h>

// Problem constants
#define Bb   16
#define Kk   16
#define Ss   512
#define Ee   512
#define Ll   16
#define Hh   8
#define KVHn 2
#define Dd   64
#define HD   (Hh*Dd)        // 512
#define KVHD (KVHn*Dd)      // 128
#define NKV  (2*KVHD)       // 256
#define BKTOT (Bb*Kk)       // 256
#define MROWS (BKTOT*Ss)    // 131072

// Scratch (static device globals)
__device__ __half g_spike_h[(size_t)MROWS * Ee];   // fp16 spike
__device__ __half g_wkv_h[NKV * Ee];               // [Wk;Wv] fp16
__device__ __half g_wo_h[Ee * HD];                 // Wo fp16
__device__ __half g_xkv_h[(size_t)MROWS * NKV];    // K(rope'd)|V fp16
__device__ __half g_xq_h[KVHn * 64 * Dd];          // q fp16, pre-scaled
__device__ __half g_att_h[(size_t)BKTOT * Ll * HD];// attention out fp16

// ---------------------------------------------------------------------------
// PTX helpers
// ---------------------------------------------------------------------------
__device__ __forceinline__ void cp_async16(uint32_t saddr, const void* gptr) {
    asm volatile("cp.async.cg.shared.global [%0], [%1], 16;"
                 :: "r"(saddr), "l"(gptr) : "memory");
}
#define CP_COMMIT() asm volatile("cp.async.commit_group;" ::: "memory")
#define CP_WAIT(n)  asm volatile("cp.async.wait_group %0;" :: "n"(n) : "memory")

__device__ __forceinline__ uint32_t lds32(uint32_t addr) {
    uint32_t v;
    asm volatile("ld.shared.b32 %0, [%1];" : "=r"(v) : "r"(addr));
    return v;
}

__device__ __forceinline__ void mma_f16(float* c, const uint32_t* a, const uint32_t* b) {
    asm volatile(
        "mma.sync.aligned.m16n8k16.row.col.f32.f16.f16.f32 "
        "{%0,%1,%2,%3}, {%4,%5,%6,%7}, {%8,%9}, {%0,%1,%2,%3};"
        : "+f"(c[0]), "+f"(c[1]), "+f"(c[2]), "+f"(c[3])
        : "r"(a[0]), "r"(a[1]), "r"(a[2]), "r"(a[3]), "r"(b[0]), "r"(b[1]));
}

__device__ __forceinline__ void ldsm_x4(uint32_t* r, uint32_t addr) {
    asm volatile("ldmatrix.sync.aligned.m8n8.x4.shared.b16 {%0,%1,%2,%3}, [%4];"
        : "=r"(r[0]), "=r"(r[1]), "=r"(r[2]), "=r"(r[3]) : "r"(addr));
}
__device__ __forceinline__ void ldsm_x4_t(uint32_t* r, uint32_t addr) {
    asm volatile("ldmatrix.sync.aligned.m8n8.x4.trans.shared.b16 {%0,%1,%2,%3}, [%4];"
        : "=r"(r[0]), "=r"(r[1]), "=r"(r[2]), "=r"(r[3]) : "r"(addr));
}

// ---------------------------------------------------------------------------
// conv_spike: fp32 -> fp16 stream (measured ~90us)
// ---------------------------------------------------------------------------
__global__ void conv_spike(const float4* __restrict__ src)
{
    const size_t n4 = (size_t)MROWS * Ee / 4;
    __half2* dst = reinterpret_cast<__half2*>(g_spike_h);
    for (size_t i = blockIdx.x * (size_t)blockDim.x + threadIdx.x;
         i < n4; i += (size_t)gridDim.x * blockDim.x) {
        float4 v = src[i];
        dst[2 * i]     = __floats2half2_rn(v.x, v.y);
        dst[2 * i + 1] = __floats2half2_rn(v.z, v.w);
    }
}

// ---------------------------------------------------------------------------
// conv_w: Wk|Wv -> g_wkv_h, Wo -> g_wo_h (fp32 -> fp16)
// ---------------------------------------------------------------------------
__global__ void conv_w(const float4* __restrict__ Wk, const float4* __restrict__ Wv,
                       const float4* __restrict__ Wo)
{
    int i = blockIdx.x * blockDim.x + threadIdx.x;
    const int wkv4 = NKV * Ee / 4;        // 32768
    const int wo4  = Ee * HD / 4;         // 65536
    if (i < wkv4) {
        const int half1 = KVHD * Ee / 4;
        float4 v = (i < half1) ? Wk[i] : Wv[i - half1];
        __half2* dst = reinterpret_cast<__half2*>(g_wkv_h);
        dst[2 * i]     = __floats2half2_rn(v.x, v.y);
        dst[2 * i + 1] = __floats2half2_rn(v.z, v.w);
    } else if (i < wkv4 + wo4) {
        int j = i - wkv4;
        float4 v = Wo[j];
        __half2* dst = reinterpret_cast<__half2*>(g_wo_h);
        dst[2 * j]     = __floats2half2_rn(v.x, v.y);
        dst[2 * j + 1] = __floats2half2_rn(v.z, v.w);
    }
}

// ---------------------------------------------------------------------------
// K1: xq = (latent_query @ Wq^T) / sqrt(D), stored fp16 grouped by kvh
// ---------------------------------------------------------------------------
__global__ void xq_kernel(const float* __restrict__ lq, const float* __restrict__ Wq)
{
    int l = blockIdx.x;
    __shared__ float qs[Ee];
    for (int e = threadIdx.x; e < Ee; e += blockDim.x) qs[e] = lq[l * Ee + e];
    __syncthreads();
    int j = threadIdx.x;
    const float* w = Wq + (size_t)j * Ee;
    float acc = 0.f;
#pragma unroll 8
    for (int e = 0; e < Ee; e++) acc += qs[e] * __ldg(&w[e]);
    int h = j >> 6, d = j & 63;
    g_xq_h[((h >> 2) * 64 + (h & 3) * 16 + l) * 64 + d] = __float2half(acc * 0.125f);
}

// ---------------------------------------------------------------------------
// K2: fp16 GEMM xkv = spike_h @ wkv_h^T, RoPE fused into epilogue (K half).
// Exact R5/R6 kernel (measured 167us). CTA 128x128, BK=32, 3-stage cp.async,
// 256 threads (4m x 2n warps, 32x64 warp tile). grid (2, 1024).
// ---------------------------------------------------------------------------
#define STGB 20480
#define GEMM16_SMEM (3 * STGB)   // 61440 bytes

__global__ void __launch_bounds__(256, 2) gemm_kv_f16(
    const int* __restrict__ offs,
    const float* __restrict__ cosT,
    const float* __restrict__ sinT)
{
    extern __shared__ char sm_raw[];
    uint32_t sbase = (uint32_t)__cvta_generic_to_shared(sm_raw);

    int tid  = threadIdx.x;
    int wid  = tid >> 5, lane = tid & 31;
    int m0   = blockIdx.y * 128;
    int n0   = blockIdx.x * 128;
    int wm   = (wid & 3) * 32;
    int wn   = (wid >> 2) * 64;

    float acc[2][8][4];
#pragma unroll
    for (int mt = 0; mt < 2; mt++)
#pragma unroll
        for (int nt = 0; nt < 8; nt++)
#pragma unroll
            for (int j = 0; j < 4; j++) acc[mt][nt][j] = 0.f;

    int lrow = tid >> 1;
    int lch  = (tid & 1) * 2;
    const __half* ag = g_spike_h + (size_t)(m0 + lrow) * Ee + lch * 8;
    const __half* bg = g_wkv_h   + (size_t)(n0 + lrow) * Ee + lch * 8;
    uint32_t dA = sbase + lrow * 80 + lch * 16;
    uint32_t dB = dA + 10240;

    auto issue = [&](int it) {
        uint32_t so = (uint32_t)(it % 3) * STGB;
        const __half* a = ag + it * 32;
        const __half* b = bg + it * 32;
        cp_async16(dA + so,      a);
        cp_async16(dA + so + 16, a + 8);
        cp_async16(dB + so,      b);
        cp_async16(dB + so + 16, b + 8);
    };

    issue(0); CP_COMMIT();
    issue(1); CP_COMMIT();

    for (int it = 0; it < 16; it++) {
        CP_WAIT(1);
        __syncthreads();
        if (it + 2 < 16) issue(it + 2);
        CP_COMMIT();

        uint32_t As = sbase + (uint32_t)(it % 3) * STGB;
        uint32_t Bs = As + 10240;
#pragma unroll
        for (int ks = 0; ks < 2; ks++) {
            int k0b = (ks * 16 + (lane & 3) * 2) * 2;
            uint32_t af[2][4], bf[8][2];
#pragma unroll
            for (int mt = 0; mt < 2; mt++) {
                uint32_t b0 = As + (uint32_t)(wm + mt * 16 + (lane >> 2)) * 80 + k0b;
                af[mt][0] = lds32(b0);
                af[mt][1] = lds32(b0 + 8 * 80);
                af[mt][2] = lds32(b0 + 16);
                af[mt][3] = lds32(b0 + 8 * 80 + 16);
            }
#pragma unroll
            for (int nt = 0; nt < 8; nt++) {
                uint32_t b0 = Bs + (uint32_t)(wn + nt * 8 + (lane >> 2)) * 80 + k0b;
                bf[nt][0] = lds32(b0);
                bf[nt][1] = lds32(b0 + 16);
            }
#pragma unroll
            for (int mt = 0; mt < 2; mt++)
#pragma unroll
                for (int nt = 0; nt < 8; nt++)
                    mma_f16(acc[mt][nt], af[mt], bf[nt]);
        }
    }

    __half2* outp = reinterpret_cast<__half2*>(g_xkv_h);
    if (n0 == 0) {
#pragma unroll
        for (int mt = 0; mt < 2; mt++) {
            int r0 = m0 + wm + mt * 16 + (lane >> 2);
            int r1 = r0 + 8;
            int o0 = __ldg(&offs[r0]) * Dd;
            int o1 = __ldg(&offs[r1]) * Dd;
#pragma unroll
            for (int nt = 0; nt < 4; nt++) {
                int dbase = nt * 8 + (lane & 3) * 2;
                float lo0[2], hi0[2], lo1[2], hi1[2];
#pragma unroll
                for (int j = 0; j < 2; j++) {
                    int d = dbase + j;
                    float c0 = __ldg(&cosT[o0 + d]), s0 = __ldg(&sinT[o0 + d]);
                    float c1 = __ldg(&cosT[o1 + d]), s1 = __ldg(&sinT[o1 + d]);
                    float u = acc[mt][nt][j],     v = acc[mt][nt + 4][j];
                    lo0[j] = u * c0 - v * s0;  hi0[j] = v * c0 + u * s0;
                    u = acc[mt][nt][j + 2];    v = acc[mt][nt + 4][j + 2];
                    lo1[j] = u * c1 - v * s1;  hi1[j] = v * c1 + u * s1;
                }
                int col = wn + dbase;
                outp[((size_t)r0 * NKV + col) >> 1]      = __floats2half2_rn(lo0[0], lo0[1]);
                outp[((size_t)r0 * NKV + col + 32) >> 1] = __floats2half2_rn(hi0[0], hi0[1]);
                outp[((size_t)r1 * NKV + col) >> 1]      = __floats2half2_rn(lo1[0], lo1[1]);
                outp[((size_t)r1 * NKV + col + 32) >> 1] = __floats2half2_rn(hi1[0], hi1[1]);
            }
        }
    } else {
#pragma unroll
        for (int mt = 0; mt < 2; mt++) {
            int r0 = m0 + wm + mt * 16 + (lane >> 2);
            int r1 = r0 + 8;
#pragma unroll
            for (int nt = 0; nt < 8; nt++) {
                int col = 128 + wn + nt * 8 + (lane & 3) * 2;
                outp[((size_t)r0 * NKV + col) >> 1] =
                    __floats2half2_rn(acc[mt][nt][0], acc[mt][nt][1]);
                outp[((size_t)r1 * NKV + col) >> 1] =
                    __floats2half2_rn(acc[mt][nt][2], acc[mt][nt][3]);
            }
        }
    }
}

// ---------------------------------------------------------------------------
// K3: tensor-core attention (measured structure; fp16 output)
// ---------------------------------------------------------------------------
#define KOFF 0
#define VOFF 73728
#define QOFF 147456
#define ROFF 156672
#define ATTN3_SMEM (ROFF + 1024)

__global__ void __launch_bounds__(256, 1) attn3(const int* __restrict__ slen)
{
    extern __shared__ char sm[];
    uint32_t sb = (uint32_t)__cvta_generic_to_shared(sm);
    int tid = threadIdx.x, lane = tid & 31, wid = tid >> 5;
    int kvh = blockIdx.x, bk = blockIdx.y;
    size_t base = (size_t)bk * Ss;
    int mt = wid & 3, nh = wid >> 2;
    int m0 = mt * 16;

#pragma unroll
    for (int i = 0; i < 16; i++) {
        int cid = tid + i * 256; int row = cid >> 3, ch = cid & 7;
        cp_async16(sb + KOFF + row * 144 + ch * 16,
                   g_xkv_h + (base + row) * NKV + kvh * 64 + ch * 8);
    }
#pragma unroll
    for (int i = 0; i < 2; i++) {
        int cid = tid + i * 256; int row = cid >> 3, ch = cid & 7;
        cp_async16(sb + QOFF + row * 144 + ch * 16,
                   g_xq_h + (kvh * 64 + row) * 64 + ch * 8);
    }
    CP_COMMIT();
#pragma unroll
    for (int i = 0; i < 16; i++) {
        int cid = tid + i * 256; int row = cid >> 3, ch = cid & 7;
        cp_async16(sb + VOFF + row * 144 + ch * 16,
                   g_xkv_h + (base + row) * NKV + 128 + kvh * 64 + ch * 8);
    }
    CP_COMMIT();

    int len = slen[bk];

    CP_WAIT(1);
    __syncthreads();

    float acc[32][4];
#pragma unroll
    for (int nf = 0; nf < 32; nf++)
#pragma unroll
        for (int j = 0; j < 4; j++) acc[nf][j] = 0.f;

    uint32_t aab = sb + QOFF + (uint32_t)(m0 + (lane & 15)) * 144 + (lane >> 4) * 16;
#pragma unroll
    for (int kt = 0; kt < 4; kt++) {
        uint32_t a[4];
        ldsm_x4(a, aab + kt * 32);
#pragma unroll
        for (int np = 0; np < 16; np++) {
            uint32_t b[4];
            ldsm_x4(b, sb + KOFF + (uint32_t)(nh * 256 + np * 16 + (lane & 15)) * 144
                         + kt * 32 + (lane >> 4) * 16);
            uint32_t bp0[2] = {b[0], b[2]}, bp1[2] = {b[1], b[3]};
            mma_f16(acc[2 * np],     a, bp0);
            mma_f16(acc[2 * np + 1], a, bp1);
        }
    }

    int scol = nh * 256 + (lane & 3) * 2;
    float mx0 = -CUDART_INF_F, mx1 = -CUDART_INF_F;
#pragma unroll
    for (int nf = 0; nf < 32; nf++) {
        int s0 = scol + nf * 8;
        if (s0 >= len)     { acc[nf][0] = -CUDART_INF_F; acc[nf][2] = -CUDART_INF_F; }
        if (s0 + 1 >= len) { acc[nf][1] = -CUDART_INF_F; acc[nf][3] = -CUDART_INF_F; }
        mx0 = fmaxf(mx0, fmaxf(acc[nf][0], acc[nf][1]));
        mx1 = fmaxf(mx1, fmaxf(acc[nf][2], acc[nf][3]));
    }
    mx0 = fmaxf(mx0, __shfl_xor_sync(0xffffffffu, mx0, 1));
    mx0 = fmaxf(mx0, __shfl_xor_sync(0xffffffffu, mx0, 2));
    mx1 = fmaxf(mx1, __shfl_xor_sync(0xffffffffu, mx1, 1));
    mx1 = fmaxf(mx1, __shfl_xor_sync(0xffffffffu, mx1, 2));

    float* redm = (float*)(sm + ROFF);
    float* reds = redm + 128;
    int r0 = m0 + (lane >> 2), r1 = r0 + 8;
    if ((lane & 3) == 0) { redm[r0 * 2 + nh] = mx0; redm[r1 * 2 + nh] = mx1; }
    __syncthreads();
    mx0 = fmaxf(redm[r0 * 2], redm[r0 * 2 + 1]);
    mx1 = fmaxf(redm[r1 * 2], redm[r1 * 2 + 1]);

    float sum0 = 0.f, sum1 = 0.f;
#pragma unroll
    for (int nf = 0; nf < 32; nf++) {
        acc[nf][0] = __expf(acc[nf][0] - mx0);
        acc[nf][1] = __expf(acc[nf][1] - mx0);
        acc[nf][2] = __expf(acc[nf][2] - mx1);
        acc[nf][3] = __expf(acc[nf][3] - mx1);
        sum0 += acc[nf][0] + acc[nf][1];
        sum1 += acc[nf][2] + acc[nf][3];
    }
    sum0 += __shfl_xor_sync(0xffffffffu, sum0, 1);
    sum0 += __shfl_xor_sync(0xffffffffu, sum0, 2);
    sum1 += __shfl_xor_sync(0xffffffffu, sum1, 1);
    sum1 += __shfl_xor_sync(0xffffffffu, sum1, 2);
    if ((lane & 3) == 0) { reds[r0 * 2 + nh] = sum0; reds[r1 * 2 + nh] = sum1; }
    __syncthreads();
    float inv0 = 1.f / (reds[r0 * 2] + reds[r0 * 2 + 1]);
    float inv1 = 1.f / (reds[r1 * 2] + reds[r1 * 2 + 1]);

#pragma unroll
    for (int nf = 0; nf < 32; nf++) {
        int s2 = scol + nf * 8;
        *(__half2*)(sm + KOFF + (size_t)r0 * 1040 + s2 * 2) =
            __floats2half2_rn(acc[nf][0], acc[nf][1]);
        *(__half2*)(sm + KOFF + (size_t)r1 * 1040 + s2 * 2) =
            __floats2half2_rn(acc[nf][2], acc[nf][3]);
    }
    CP_WAIT(0);
    __syncthreads();

    float oc[4][4];
#pragma unroll
    for (int i = 0; i < 4; i++)
#pragma unroll
        for (int j = 0; j < 4; j++) oc[i][j] = 0.f;

    uint32_t pab = sb + KOFF + (uint32_t)(m0 + (lane & 15)) * 1040 + (lane >> 4) * 16;
    int dbase = nh * 32;
#pragma unroll 4
    for (int kt = 0; kt < 32; kt++) {
        uint32_t a[4];
        ldsm_x4(a, pab + kt * 32);
        uint32_t vaddr = sb + VOFF + (uint32_t)(kt * 16 + (lane & 15)) * 144
                       + (dbase + (lane >> 4) * 8) * 2;
        uint32_t b[4];
        ldsm_x4_t(b, vaddr);
        {
            uint32_t bp0[2] = {b[0], b[1]}, bp1[2] = {b[2], b[3]};
            mma_f16(oc[0], a, bp0);
            mma_f16(oc[1], a, bp1);
        }
        ldsm_x4_t(b, vaddr + 32);
        {
            uint32_t bp0[2] = {b[0], b[1]}, bp1[2] = {b[2], b[3]};
            mma_f16(oc[2], a, bp0);
            mma_f16(oc[3], a, bp1);
        }
    }

    __half* orow0 = g_att_h + (((size_t)bk * Ll + (r0 & 15)) * Hh + kvh * 4 + (r0 >> 4)) * Dd;
    __half* orow1 = g_att_h + (((size_t)bk * Ll + (r1 & 15)) * Hh + kvh * 4 + (r1 >> 4)) * Dd;
#pragma unroll
    for (int nf = 0; nf < 4; nf++) {
        int d = dbase + nf * 8 + (lane & 3) * 2;
        *(__half2*)(orow0 + d) = __floats2half2_rn(oc[nf][0] * inv0, oc[nf][1] * inv0);
        *(__half2*)(orow1 + d) = __floats2half2_rn(oc[nf][2] * inv1, oc[nf][3] * inv1);
    }
}

// ---------------------------------------------------------------------------
// K4: fp16 NT GEMM out = att_h @ Wo_h^T  (fp32 out). 128x128 tile, 3-stage.
// ---------------------------------------------------------------------------
#define K4_SMEM 61440

__global__ void __launch_bounds__(256, 2) gemm_out16(float* __restrict__ C)
{
    extern __shared__ char sm_raw[];
    uint32_t sb = (uint32_t)__cvta_generic_to_shared(sm_raw);

    int tid  = threadIdx.x;
    int wid  = tid >> 5, lane = tid & 31;
    int n0   = blockIdx.x * 128;
    int m0   = blockIdx.y * 128;
    int wm   = (wid & 3) * 32;
    int wn   = (wid >> 2) * 64;

    float acc[2][8][4];
#pragma unroll
    for (int mt = 0; mt < 2; mt++)
#pragma unroll
        for (int nt = 0; nt < 8; nt++)
#pragma unroll
            for (int j = 0; j < 4; j++) acc[mt][nt][j] = 0.f;

    int lrow = tid >> 1, lch = (tid & 1);
    const __half* agp = g_att_h + (size_t)(m0 + lrow) * HD + lch * 16;
    const __half* bgp = g_wo_h  + (size_t)(n0 + lrow) * HD + lch * 16;
    uint32_t asd = sb + (uint32_t)lrow * 80 + lch * 32;
    uint32_t bsd = asd + 30720;

    auto issue = [&](int it) {
        uint32_t so = (uint32_t)(it % 3) * 10240;
        const __half* a = agp + it * 32;
        const __half* b = bgp + it * 32;
        cp_async16(asd + so,      a);
        cp_async16(asd + so + 16, a + 8);
        cp_async16(bsd + so,      b);
        cp_async16(bsd + so + 16, b + 8);
    };

    issue(0); CP_COMMIT();
    issue(1); CP_COMMIT();

    for (int it = 0; it < 16; it++) {
        CP_WAIT(1);
        __syncthreads();
        if (it + 2 < 16) issue(it + 2);
        CP_COMMIT();

        uint32_t As = sb + (uint32_t)(it % 3) * 10240;
        uint32_t Bs = As + 30720;
#pragma unroll
        for (int ks = 0; ks < 2; ks++) {
            int k0b = (ks * 16 + (lane & 3) * 2) * 2;
            uint32_t af[2][4], bf[8][2];
#pragma unroll
            for (int mt = 0; mt < 2; mt++) {
                uint32_t b0 = As + (uint32_t)(wm + mt * 16 + (lane >> 2)) * 80 + k0b;
                af[mt][0] = lds32(b0);
                af[mt][1] = lds32(b0 + 8 * 80);
                af[mt][2] = lds32(b0 + 16);
                af[mt][3] = lds32(b0 + 8 * 80 + 16);
            }
#pragma unroll
            for (int nt = 0; nt < 8; nt++) {
                uint32_t b0 = Bs + (uint32_t)(wn + nt * 8 + (lane >> 2)) * 80 + k0b;
                bf[nt][0] = lds32(b0);
                bf[nt][1] = lds32(b0 + 16);
            }
#pragma unroll
            for (int mt = 0; mt < 2; mt++)
#pragma unroll
                for (int nt = 0; nt < 8; nt++)
                    mma_f16(acc[mt][nt], af[mt], bf[nt]);
        }
    }

#pragma unroll
    for (int mt = 0; mt < 2; mt++) {
        int row = m0 + wm + mt * 16 + (lane >> 2);
#pragma unroll
        for (int nt = 0; nt < 8; nt++) {
            int col = n0 + wn + nt * 8 + (lane & 3) * 2;
            *reinterpret_cast<float2*>(C + (size_t)row * Ee + col) =
                make_float2(acc[mt][nt][0], acc[mt][nt][1]);
            *reinterpret_cast<float2*>(C + (size_t)(row + 8) * Ee + col) =
                make_float2(acc[mt][nt][2], acc[mt][nt][3]);
        }
    }
}

// ---------------------------------------------------------------------------
extern "C" void kernel_launch(void* const* d_in, const int* in_sizes, int n_in,
                              void* d_out, int out_size)
{
    const float* spike  = (const float*)d_in[0];
    const int*   offs   = (const int*)  d_in[1];
    const int*   slen   = (const int*)  d_in[2];
    const float* cosT   = (const float*)d_in[3];
    const float* sinT   = (const float*)d_in[4];
    const float* lq     = (const float*)d_in[5];
    const float* Wq     = (const float*)d_in[6];
    const float* Wk     = (const float*)d_in[7];
    const float* Wv     = (const float*)d_in[8];
    const float* Wo     = (const float*)d_in[9];
    float* out = (float*)d_out;

    cudaFuncSetAttribute(gemm_kv_f16,
                         cudaFuncAttributeMaxDynamicSharedMemorySize, GEMM16_SMEM);
    cudaFuncSetAttribute(attn3,
                         cudaFuncAttributeMaxDynamicSharedMemorySize, ATTN3_SMEM);
    cudaFuncSetAttribute(gemm_out16,
                         cudaFuncAttributeMaxDynamicSharedMemorySize, K4_SMEM);

    // Converts + queries
    conv_spike<<<4096, 256>>>((const float4*)spike);
    conv_w<<<384, 256>>>((const float4*)Wk, (const float4*)Wv, (const float4*)Wo);
    xq_kernel<<<Ll, Ee>>>(lq, Wq);

    // K2: fp16 K|V projection with fused RoPE epilogue (measured 167us)
    gemm_kv_f16<<<dim3(2, MROWS / 128), 256, GEMM16_SMEM>>>(offs, cosT, sinT);

    // K3: tensor-core attention (fp16 output)
    attn3<<<dim3(KVHn, BKTOT), 256, ATTN3_SMEM>>>(slen);

    // K4: output projection (fp16 inputs, fp32 out)
    gemm_out16<<<dim3(4, 32), 256, K4_SMEM>>>(out);
}

// round 17
// speedup vs baseline: 1.1286x; 1.1286x over previous
#include <cuda_runtime.h>
#include <cuda_fp16.h>
#include <math.h>
#include <math_constants.h>
#include <stdint.h>

// Problem constants
#define Bb   16
#define Kk   16
#define Ss   512
#define Ee   512
#define Ll   16
#define Hh   8
#define KVHn 2
#define Dd   64
#define HD   (Hh*Dd)        // 512
#define KVHD (KVHn*Dd)      // 128
#define NKV  (2*KVHD)       // 256
#define BKTOT (Bb*Kk)       // 256
#define MROWS (BKTOT*Ss)    // 131072

// Scratch (static device globals)
__device__ __half g_wkv_h[NKV * Ee];               // [Wk;Wv] fp16
__device__ __half g_wo_h[Ee * HD];                 // Wo fp16
__device__ __half g_xkv_h[(size_t)MROWS * NKV];    // K(rope'd)|V fp16
__device__ __half g_xq_h[KVHn * 64 * Dd];          // q fp16, pre-scaled
__device__ __half g_att_h[(size_t)BKTOT * Ll * HD];// attention out fp16

// ---------------------------------------------------------------------------
// PTX helpers
// ---------------------------------------------------------------------------
__device__ __forceinline__ void cp_async16(uint32_t saddr, const void* gptr) {
    asm volatile("cp.async.cg.shared.global [%0], [%1], 16;"
                 :: "r"(saddr), "l"(gptr) : "memory");
}
#define CP_COMMIT() asm volatile("cp.async.commit_group;" ::: "memory")
#define CP_WAIT(n)  asm volatile("cp.async.wait_group %0;" :: "n"(n) : "memory")

__device__ __forceinline__ uint32_t lds32(uint32_t addr) {
    uint32_t v;
    asm volatile("ld.shared.b32 %0, [%1];" : "=r"(v) : "r"(addr));
    return v;
}

__device__ __forceinline__ void mma_f16(float* c, const uint32_t* a, const uint32_t* b) {
    asm volatile(
        "mma.sync.aligned.m16n8k16.row.col.f32.f16.f16.f32 "
        "{%0,%1,%2,%3}, {%4,%5,%6,%7}, {%8,%9}, {%0,%1,%2,%3};"
        : "+f"(c[0]), "+f"(c[1]), "+f"(c[2]), "+f"(c[3])
        : "r"(a[0]), "r"(a[1]), "r"(a[2]), "r"(a[3]), "r"(b[0]), "r"(b[1]));
}

__device__ __forceinline__ void ldsm_x4(uint32_t* r, uint32_t addr) {
    asm volatile("ldmatrix.sync.aligned.m8n8.x4.shared.b16 {%0,%1,%2,%3}, [%4];"
        : "=r"(r[0]), "=r"(r[1]), "=r"(r[2]), "=r"(r[3]) : "r"(addr));
}
__device__ __forceinline__ void ldsm_x4_t(uint32_t* r, uint32_t addr) {
    asm volatile("ldmatrix.sync.aligned.m8n8.x4.trans.shared.b16 {%0,%1,%2,%3}, [%4];"
        : "=r"(r[0]), "=r"(r[1]), "=r"(r[2]), "=r"(r[3]) : "r"(addr));
}

// ---------------------------------------------------------------------------
// conv_w: Wk|Wv -> g_wkv_h, Wo -> g_wo_h (fp32 -> fp16)
// ---------------------------------------------------------------------------
__global__ void conv_w(const float4* __restrict__ Wk, const float4* __restrict__ Wv,
                       const float4* __restrict__ Wo)
{
    int i = blockIdx.x * blockDim.x + threadIdx.x;
    const int wkv4 = NKV * Ee / 4;        // 32768
    const int wo4  = Ee * HD / 4;         // 65536
    if (i < wkv4) {
        const int half1 = KVHD * Ee / 4;
        float4 v = (i < half1) ? Wk[i] : Wv[i - half1];
        __half2* dst = reinterpret_cast<__half2*>(g_wkv_h);
        dst[2 * i]     = __floats2half2_rn(v.x, v.y);
        dst[2 * i + 1] = __floats2half2_rn(v.z, v.w);
    } else if (i < wkv4 + wo4) {
        int j = i - wkv4;
        float4 v = Wo[j];
        __half2* dst = reinterpret_cast<__half2*>(g_wo_h);
        dst[2 * j]     = __floats2half2_rn(v.x, v.y);
        dst[2 * j + 1] = __floats2half2_rn(v.z, v.w);
    }
}

// ---------------------------------------------------------------------------
// K1: xq = (latent_query @ Wq^T) / sqrt(D), stored fp16 grouped by kvh
// ---------------------------------------------------------------------------
__global__ void xq_kernel(const float* __restrict__ lq, const float* __restrict__ Wq)
{
    int l = blockIdx.x;
    __shared__ float qs[Ee];
    for (int e = threadIdx.x; e < Ee; e += blockDim.x) qs[e] = lq[l * Ee + e];
    __syncthreads();
    int j = threadIdx.x;
    const float* w = Wq + (size_t)j * Ee;
    float acc = 0.f;
#pragma unroll 8
    for (int e = 0; e < Ee; e++) acc += qs[e] * __ldg(&w[e]);
    int h = j >> 6, d = j & 63;
    g_xq_h[((h >> 2) * 64 + (h & 3) * 16 + l) * 64 + d] = __float2half(acc * 0.125f);
}

// ---------------------------------------------------------------------------
// K2 fused v3: fp32 spike cp.async + in-smem convert + fp16 GEMM, RoPE epi.
// CTA 128m x 256n, 512 threads (16 warps 4m x 4n), warp tile 32x64.
// Staging: A32 x3, B x4, Ah x2. Group G(it)={A32(it),B(it)}.
// Iter it: wait(<=1 | 0 at tail) -> sync -> issue G(it+3) -> convert(it+1)
//          -> mma(it).  ONE barrier per iter; all cross-thread cp.async
//          reads are preceded by wait+barrier; per-segment buffer sets are
//          disjoint (A32: it%3 w vs (it+1)%3 r; B: (it+3)%4 w vs it%4 r;
//          Ah: (it+1)&1 w vs it&1 r).
// smem: A32 3x16384 | B 4x20480 | Ah 2x10240 = 151552 bytes.  occ 1.
// ---------------------------------------------------------------------------
#define A32OFF 0
#define BOFF   49152
#define AHOFF  131072
#define K2_SMEM 151552

__global__ void __launch_bounds__(512, 1) gemm_kv_fused(
    const float* __restrict__ spike,
    const int* __restrict__ offs,
    const float* __restrict__ cosT,
    const float* __restrict__ sinT)
{
    extern __shared__ char sm_raw[];
    uint32_t sb = (uint32_t)__cvta_generic_to_shared(sm_raw);

    int tid  = threadIdx.x;
    int wid  = tid >> 5, lane = tid & 31;
    int m0   = blockIdx.x * 128;
    int wm   = (wid & 3) * 32;
    int wn   = (wid >> 2) * 64;

    float acc[2][8][4];
#pragma unroll
    for (int mt = 0; mt < 2; mt++)
#pragma unroll
        for (int nt = 0; nt < 8; nt++)
#pragma unroll
            for (int j = 0; j < 4; j++) acc[mt][nt][j] = 0.f;

    // A32 loader: 1024 16B-chunks; thread -> chunks tid, tid+512
    int arow0 = tid >> 3,          ach0 = tid & 7;
    int arow1 = (tid + 512) >> 3,  ach1 = (tid + 512) & 7;
    const float* agp0 = spike + (size_t)(m0 + arow0) * Ee + ach0 * 4;
    const float* agp1 = spike + (size_t)(m0 + arow1) * Ee + ach1 * 4;
    uint32_t asd0 = sb + A32OFF + (uint32_t)arow0 * 128 + ach0 * 16;
    uint32_t asd1 = sb + A32OFF + (uint32_t)arow1 * 128 + ach1 * 16;

    // B loader: 1024 16B-chunks; 256 rows x 4 chunks, row stride 80B
    int brow0 = tid >> 2,          bch0 = tid & 3;
    int brow1 = (tid + 512) >> 2,  bch1 = (tid + 512) & 3;
    const __half* bgp0 = g_wkv_h + (size_t)brow0 * Ee + bch0 * 8;
    const __half* bgp1 = g_wkv_h + (size_t)brow1 * Ee + bch1 * 8;
    uint32_t bsd0 = sb + BOFF + (uint32_t)brow0 * 80 + bch0 * 16;
    uint32_t bsd1 = sb + BOFF + (uint32_t)brow1 * 80 + bch1 * 16;

    auto issue = [&](int it) {
        uint32_t ao = (uint32_t)(it % 3) * 16384;
        uint32_t bo = (uint32_t)(it % 4) * 20480;
        int kc = it * 32;
        cp_async16(asd0 + ao, agp0 + kc);
        cp_async16(asd1 + ao, agp1 + kc);
        cp_async16(bsd0 + bo, bgp0 + kc);
        cp_async16(bsd1 + bo, bgp1 + kc);
        CP_COMMIT();
    };

    // convert mapping: thread -> 8 floats: row = tid>>2, col = (tid&3)*8
    int crow = tid >> 2, ccol = (tid & 3) * 8;
    uint32_t csrc = sb + A32OFF + (uint32_t)crow * 128 + ccol * 4;
    uint32_t cdst = sb + AHOFF + (uint32_t)crow * 80 + ccol * 2;

    auto convert = [&](int it) {    // A32[it%3] -> Ah[it&1]
        uint32_t so  = (uint32_t)(it % 3) * 16384;
        uint32_t dso = (uint32_t)(it & 1) * 10240;
        float4 v0, v1;
        asm volatile("ld.shared.v4.f32 {%0,%1,%2,%3}, [%4];"
            : "=f"(v0.x), "=f"(v0.y), "=f"(v0.z), "=f"(v0.w) : "r"(csrc + so));
        asm volatile("ld.shared.v4.f32 {%0,%1,%2,%3}, [%4];"
            : "=f"(v1.x), "=f"(v1.y), "=f"(v1.z), "=f"(v1.w) : "r"(csrc + so + 16));
        __half2 h0 = __floats2half2_rn(v0.x, v0.y);
        __half2 h1 = __floats2half2_rn(v0.z, v0.w);
        __half2 h2 = __floats2half2_rn(v1.x, v1.y);
        __half2 h3 = __floats2half2_rn(v1.z, v1.w);
        asm volatile("st.shared.v4.b32 [%0], {%1,%2,%3,%4};"
            :: "r"(cdst + dso),
               "r"(*(uint32_t*)&h0), "r"(*(uint32_t*)&h1),
               "r"(*(uint32_t*)&h2), "r"(*(uint32_t*)&h3) : "memory");
    };

    // Prologue: G0..G2; publish G0; convert(0) -> Ah[0]
    issue(0);
    issue(1);
    issue(2);
    CP_WAIT(2);            // G0 complete (<=2 pending)
    __syncthreads();       // publish G0 across threads
    convert(0);

    for (int it = 0; it < 16; it++) {
        // guarantee G(it+1) complete (newest committed is G(it+2))
        if (it >= 14) { CP_WAIT(0); } else { CP_WAIT(1); }
        __syncthreads();                      // publish + segment fence

        if (it + 3 < 16) issue(it + 3);       // writes A32[it%3], B[(it+3)%4]
        if (it + 1 < 16) convert(it + 1);     // reads A32[(it+1)%3] -> Ah[(it+1)&1]

        uint32_t Ah = sb + AHOFF + (uint32_t)(it & 1) * 10240;
        uint32_t Bs = sb + BOFF  + (uint32_t)(it % 4) * 20480;
#pragma unroll
        for (int ks = 0; ks < 2; ks++) {
            int k0b = (ks * 16 + (lane & 3) * 2) * 2;
            uint32_t af[2][4], bf[8][2];
#pragma unroll
            for (int mt = 0; mt < 2; mt++) {
                uint32_t b0 = Ah + (uint32_t)(wm + mt * 16 + (lane >> 2)) * 80 + k0b;
                af[mt][0] = lds32(b0);
                af[mt][1] = lds32(b0 + 8 * 80);
                af[mt][2] = lds32(b0 + 16);
                af[mt][3] = lds32(b0 + 8 * 80 + 16);
            }
#pragma unroll
            for (int nt = 0; nt < 8; nt++) {
                uint32_t b0 = Bs + (uint32_t)(wn + nt * 8 + (lane >> 2)) * 80 + k0b;
                bf[nt][0] = lds32(b0);
                bf[nt][1] = lds32(b0 + 16);
            }
#pragma unroll
            for (int mt = 0; mt < 2; mt++)
#pragma unroll
                for (int nt = 0; nt < 8; nt++)
                    mma_f16(acc[mt][nt], af[mt], bf[nt]);
        }
    }

    // Epilogue -> fp16 xkv; RoPE on K cols (wn < 128), direct store for V.
    __half2* outp = reinterpret_cast<__half2*>(g_xkv_h);
    if (wn < 128) {
#pragma unroll
        for (int mt = 0; mt < 2; mt++) {
            int r0 = m0 + wm + mt * 16 + (lane >> 2);
            int r1 = r0 + 8;
            int o0 = __ldg(&offs[r0]) * Dd;
            int o1 = __ldg(&offs[r1]) * Dd;
#pragma unroll
            for (int nt = 0; nt < 4; nt++) {
                int dbase = nt * 8 + (lane & 3) * 2;   // local d in [0,32)
                float lo0[2], hi0[2], lo1[2], hi1[2];
#pragma unroll
                for (int j = 0; j < 2; j++) {
                    int d = dbase + j;
                    float c0 = __ldg(&cosT[o0 + d]), s0 = __ldg(&sinT[o0 + d]);
                    float c1 = __ldg(&cosT[o1 + d]), s1 = __ldg(&sinT[o1 + d]);
                    float u = acc[mt][nt][j],     v = acc[mt][nt + 4][j];
                    lo0[j] = u * c0 - v * s0;  hi0[j] = v * c0 + u * s0;
                    u = acc[mt][nt][j + 2];    v = acc[mt][nt + 4][j + 2];
                    lo1[j] = u * c1 - v * s1;  hi1[j] = v * c1 + u * s1;
                }
                int col = wn + dbase;                  // 0..127 even
                outp[((size_t)r0 * NKV + col) >> 1]      = __floats2half2_rn(lo0[0], lo0[1]);
                outp[((size_t)r0 * NKV + col + 32) >> 1] = __floats2half2_rn(hi0[0], hi0[1]);
                outp[((size_t)r1 * NKV + col) >> 1]      = __floats2half2_rn(lo1[0], lo1[1]);
                outp[((size_t)r1 * NKV + col + 32) >> 1] = __floats2half2_rn(hi1[0], hi1[1]);
            }
        }
    } else {
#pragma unroll
        for (int mt = 0; mt < 2; mt++) {
            int r0 = m0 + wm + mt * 16 + (lane >> 2);
            int r1 = r0 + 8;
#pragma unroll
            for (int nt = 0; nt < 8; nt++) {
                int col = wn + nt * 8 + (lane & 3) * 2;   // 128..255
                outp[((size_t)r0 * NKV + col) >> 1] =
                    __floats2half2_rn(acc[mt][nt][0], acc[mt][nt][1]);
                outp[((size_t)r1 * NKV + col) >> 1] =
                    __floats2half2_rn(acc[mt][nt][2], acc[mt][nt][3]);
            }
        }
    }
}

// ---------------------------------------------------------------------------
// K3: tensor-core attention (measured; fp16 output)
// ---------------------------------------------------------------------------
#define KOFF 0
#define VOFF 73728
#define QOFF 147456
#define ROFF 156672
#define ATTN3_SMEM (ROFF + 1024)

__global__ void __launch_bounds__(256, 1) attn3(const int* __restrict__ slen)
{
    extern __shared__ char sm[];
    uint32_t sb = (uint32_t)__cvta_generic_to_shared(sm);
    int tid = threadIdx.x, lane = tid & 31, wid = tid >> 5;
    int kvh = blockIdx.x, bk = blockIdx.y;
    size_t base = (size_t)bk * Ss;
    int mt = wid & 3, nh = wid >> 2;
    int m0 = mt * 16;

#pragma unroll
    for (int i = 0; i < 16; i++) {
        int cid = tid + i * 256; int row = cid >> 3, ch = cid & 7;
        cp_async16(sb + KOFF + row * 144 + ch * 16,
                   g_xkv_h + (base + row) * NKV + kvh * 64 + ch * 8);
    }
#pragma unroll
    for (int i = 0; i < 2; i++) {
        int cid = tid + i * 256; int row = cid >> 3, ch = cid & 7;
        cp_async16(sb + QOFF + row * 144 + ch * 16,
                   g_xq_h + (kvh * 64 + row) * 64 + ch * 8);
    }
    CP_COMMIT();
#pragma unroll
    for (int i = 0; i < 16; i++) {
        int cid = tid + i * 256; int row = cid >> 3, ch = cid & 7;
        cp_async16(sb + VOFF + row * 144 + ch * 16,
                   g_xkv_h + (base + row) * NKV + 128 + kvh * 64 + ch * 8);
    }
    CP_COMMIT();

    int len = slen[bk];

    CP_WAIT(1);
    __syncthreads();

    float acc[32][4];
#pragma unroll
    for (int nf = 0; nf < 32; nf++)
#pragma unroll
        for (int j = 0; j < 4; j++) acc[nf][j] = 0.f;

    uint32_t aab = sb + QOFF + (uint32_t)(m0 + (lane & 15)) * 144 + (lane >> 4) * 16;
#pragma unroll
    for (int kt = 0; kt < 4; kt++) {
        uint32_t a[4];
        ldsm_x4(a, aab + kt * 32);
#pragma unroll
        for (int np = 0; np < 16; np++) {
            uint32_t b[4];
            ldsm_x4(b, sb + KOFF + (uint32_t)(nh * 256 + np * 16 + (lane & 15)) * 144
                         + kt * 32 + (lane >> 4) * 16);
            uint32_t bp0[2] = {b[0], b[2]}, bp1[2] = {b[1], b[3]};
            mma_f16(acc[2 * np],     a, bp0);
            mma_f16(acc[2 * np + 1], a, bp1);
        }
    }

    int scol = nh * 256 + (lane & 3) * 2;
    float mx0 = -CUDART_INF_F, mx1 = -CUDART_INF_F;
#pragma unroll
    for (int nf = 0; nf < 32; nf++) {
        int s0 = scol + nf * 8;
        if (s0 >= len)     { acc[nf][0] = -CUDART_INF_F; acc[nf][2] = -CUDART_INF_F; }
        if (s0 + 1 >= len) { acc[nf][1] = -CUDART_INF_F; acc[nf][3] = -CUDART_INF_F; }
        mx0 = fmaxf(mx0, fmaxf(acc[nf][0], acc[nf][1]));
        mx1 = fmaxf(mx1, fmaxf(acc[nf][2], acc[nf][3]));
    }
    mx0 = fmaxf(mx0, __shfl_xor_sync(0xffffffffu, mx0, 1));
    mx0 = fmaxf(mx0, __shfl_xor_sync(0xffffffffu, mx0, 2));
    mx1 = fmaxf(mx1, __shfl_xor_sync(0xffffffffu, mx1, 1));
    mx1 = fmaxf(mx1, __shfl_xor_sync(0xffffffffu, mx1, 2));

    float* redm = (float*)(sm + ROFF);
    float* reds = redm + 128;
    int r0 = m0 + (lane >> 2), r1 = r0 + 8;
    if ((lane & 3) == 0) { redm[r0 * 2 + nh] = mx0; redm[r1 * 2 + nh] = mx1; }
    __syncthreads();
    mx0 = fmaxf(redm[r0 * 2], redm[r0 * 2 + 1]);
    mx1 = fmaxf(redm[r1 * 2], redm[r1 * 2 + 1]);

    float sum0 = 0.f, sum1 = 0.f;
#pragma unroll
    for (int nf = 0; nf < 32; nf++) {
        acc[nf][0] = __expf(acc[nf][0] - mx0);
        acc[nf][1] = __expf(acc[nf][1] - mx0);
        acc[nf][2] = __expf(acc[nf][2] - mx1);
        acc[nf][3] = __expf(acc[nf][3] - mx1);
        sum0 += acc[nf][0] + acc[nf][1];
        sum1 += acc[nf][2] + acc[nf][3];
    }
    sum0 += __shfl_xor_sync(0xffffffffu, sum0, 1);
    sum0 += __shfl_xor_sync(0xffffffffu, sum0, 2);
    sum1 += __shfl_xor_sync(0xffffffffu, sum1, 1);
    sum1 += __shfl_xor_sync(0xffffffffu, sum1, 2);
    if ((lane & 3) == 0) { reds[r0 * 2 + nh] = sum0; reds[r1 * 2 + nh] = sum1; }
    __syncthreads();
    float inv0 = 1.f / (reds[r0 * 2] + reds[r0 * 2 + 1]);
    float inv1 = 1.f / (reds[r1 * 2] + reds[r1 * 2 + 1]);

#pragma unroll
    for (int nf = 0; nf < 32; nf++) {
        int s2 = scol + nf * 8;
        *(__half2*)(sm + KOFF + (size_t)r0 * 1040 + s2 * 2) =
            __floats2half2_rn(acc[nf][0], acc[nf][1]);
        *(__half2*)(sm + KOFF + (size_t)r1 * 1040 + s2 * 2) =
            __floats2half2_rn(acc[nf][2], acc[nf][3]);
    }
    CP_WAIT(0);
    __syncthreads();

    float oc[4][4];
#pragma unroll
    for (int i = 0; i < 4; i++)
#pragma unroll
        for (int j = 0; j < 4; j++) oc[i][j] = 0.f;

    uint32_t pab = sb + KOFF + (uint32_t)(m0 + (lane & 15)) * 1040 + (lane >> 4) * 16;
    int dbase = nh * 32;
#pragma unroll 4
    for (int kt = 0; kt < 32; kt++) {
        uint32_t a[4];
        ldsm_x4(a, pab + kt * 32);
        uint32_t vaddr = sb + VOFF + (uint32_t)(kt * 16 + (lane & 15)) * 144
                       + (dbase + (lane >> 4) * 8) * 2;
        uint32_t b[4];
        ldsm_x4_t(b, vaddr);
        {
            uint32_t bp0[2] = {b[0], b[1]}, bp1[2] = {b[2], b[3]};
            mma_f16(oc[0], a, bp0);
            mma_f16(oc[1], a, bp1);
        }
        ldsm_x4_t(b, vaddr + 32);
        {
            uint32_t bp0[2] = {b[0], b[1]}, bp1[2] = {b[2], b[3]};
            mma_f16(oc[2], a, bp0);
            mma_f16(oc[3], a, bp1);
        }
    }

    __half* orow0 = g_att_h + (((size_t)bk * Ll + (r0 & 15)) * Hh + kvh * 4 + (r0 >> 4)) * Dd;
    __half* orow1 = g_att_h + (((size_t)bk * Ll + (r1 & 15)) * Hh + kvh * 4 + (r1 >> 4)) * Dd;
#pragma unroll
    for (int nf = 0; nf < 4; nf++) {
        int d = dbase + nf * 8 + (lane & 3) * 2;
        *(__half2*)(orow0 + d) = __floats2half2_rn(oc[nf][0] * inv0, oc[nf][1] * inv0);
        *(__half2*)(orow1 + d) = __floats2half2_rn(oc[nf][2] * inv1, oc[nf][3] * inv1);
    }
}

// ---------------------------------------------------------------------------
// K4: fp16 NT GEMM out = att_h @ Wo_h^T  (fp32 out). 128x128 tile, 3-stage.
// ---------------------------------------------------------------------------
#define K4_SMEM 61440

__global__ void __launch_bounds__(256, 2) gemm_out16(float* __restrict__ C)
{
    extern __shared__ char sm_raw[];
    uint32_t sb = (uint32_t)__cvta_generic_to_shared(sm_raw);

    int tid  = threadIdx.x;
    int wid  = tid >> 5, lane = tid & 31;
    int n0   = blockIdx.x * 128;
    int m0   = blockIdx.y * 128;
    int wm   = (wid & 3) * 32;
    int wn   = (wid >> 2) * 64;

    float acc[2][8][4];
#pragma unroll
    for (int mt = 0; mt < 2; mt++)
#pragma unroll
        for (int nt = 0; nt < 8; nt++)
#pragma unroll
            for (int j = 0; j < 4; j++) acc[mt][nt][j] = 0.f;

    int lrow = tid >> 1, lch = (tid & 1);
    const __half* agp = g_att_h + (size_t)(m0 + lrow) * HD + lch * 16;
    const __half* bgp = g_wo_h  + (size_t)(n0 + lrow) * HD + lch * 16;
    uint32_t asd = sb + (uint32_t)lrow * 80 + lch * 32;
    uint32_t bsd = asd + 30720;

    auto issue = [&](int it) {
        uint32_t so = (uint32_t)(it % 3) * 10240;
        const __half* a = agp + it * 32;
        const __half* b = bgp + it * 32;
        cp_async16(asd + so,      a);
        cp_async16(asd + so + 16, a + 8);
        cp_async16(bsd + so,      b);
        cp_async16(bsd + so + 16, b + 8);
    };

    issue(0); CP_COMMIT();
    issue(1); CP_COMMIT();

    for (int it = 0; it < 16; it++) {
        CP_WAIT(1);
        __syncthreads();
        if (it + 2 < 16) issue(it + 2);
        CP_COMMIT();

        uint32_t As = sb + (uint32_t)(it % 3) * 10240;
        uint32_t Bs = As + 30720;
#pragma unroll
        for (int ks = 0; ks < 2; ks++) {
            int k0b = (ks * 16 + (lane & 3) * 2) * 2;
            uint32_t af[2][4], bf[8][2];
#pragma unroll
            for (int mt = 0; mt < 2; mt++) {
                uint32_t b0 = As + (uint32_t)(wm + mt * 16 + (lane >> 2)) * 80 + k0b;
                af[mt][0] = lds32(b0);
                af[mt][1] = lds32(b0 + 8 * 80);
                af[mt][2] = lds32(b0 + 16);
                af[mt][3] = lds32(b0 + 8 * 80 + 16);
            }
#pragma unroll
            for (int nt = 0; nt < 8; nt++) {
                uint32_t b0 = Bs + (uint32_t)(wn + nt * 8 + (lane >> 2)) * 80 + k0b;
                bf[nt][0] = lds32(b0);
                bf[nt][1] = lds32(b0 + 16);
            }
#pragma unroll
            for (int mt = 0; mt < 2; mt++)
#pragma unroll
                for (int nt = 0; nt < 8; nt++)
                    mma_f16(acc[mt][nt], af[mt], bf[nt]);
        }
    }

#pragma unroll
    for (int mt = 0; mt < 2; mt++) {
        int row = m0 + wm + mt * 16 + (lane >> 2);
#pragma unroll
        for (int nt = 0; nt < 8; nt++) {
            int col = n0 + wn + nt * 8 + (lane & 3) * 2;
            *reinterpret_cast<float2*>(C + (size_t)row * Ee + col) =
                make_float2(acc[mt][nt][0], acc[mt][nt][1]);
            *reinterpret_cast<float2*>(C + (size_t)(row + 8) * Ee + col) =
                make_float2(acc[mt][nt][2], acc[mt][nt][3]);
        }
    }
}

// ---------------------------------------------------------------------------
extern "C" void kernel_launch(void* const* d_in, const int* in_sizes, int n_in,
                              void* d_out, int out_size)
{
    const float* spike  = (const float*)d_in[0];
    const int*   offs   = (const int*)  d_in[1];
    const int*   slen   = (const int*)  d_in[2];
    const float* cosT   = (const float*)d_in[3];
    const float* sinT   = (const float*)d_in[4];
    const float* lq     = (const float*)d_in[5];
    const float* Wq     = (const float*)d_in[6];
    const float* Wk     = (const float*)d_in[7];
    const float* Wv     = (const float*)d_in[8];
    const float* Wo     = (const float*)d_in[9];
    float* out = (float*)d_out;

    cudaFuncSetAttribute(gemm_kv_fused,
                         cudaFuncAttributeMaxDynamicSharedMemorySize, K2_SMEM);
    cudaFuncSetAttribute(attn3,
                         cudaFuncAttributeMaxDynamicSharedMemorySize, ATTN3_SMEM);
    cudaFuncSetAttribute(gemm_out16,
                         cudaFuncAttributeMaxDynamicSharedMemorySize, K4_SMEM);

    // Weights fp16 + queries (small)
    conv_w<<<384, 256>>>((const float4*)Wk, (const float4*)Wv, (const float4*)Wo);
    xq_kernel<<<Ll, Ee>>>(lq, Wq);

    // K2: fused convert + fp16 K|V projection with RoPE epilogue
    gemm_kv_fused<<<MROWS / 128, 512, K2_SMEM>>>(spike, offs, cosT, sinT);

    // K3: tensor-core attention (fp16 output)
    attn3<<<dim3(KVHn, BKTOT), 256, ATTN3_SMEM>>>(slen);

    // K4: output projection (fp16 inputs, fp32 out)
    gemm_out16<<<dim3(4, 32), 256, K4_SMEM>>>(out);
}